// round 7
// baseline (speedup 1.0000x reference)
#include <cuda_runtime.h>
#include <math_constants.h>

// Problem constants: B=512, T=512, D=128, H=128
#define BB 512
#define TT 512
#define DD 128
#define HH 128

// ---------------- scratch (static __device__ allowed) ----------------
__device__ float g_r [BB * DD];          // r vector per batch      (256 KB)
__device__ float g_vp[BB * 4 * DD];      // partial v per (b,quarter) (1 MB)
__device__ float g_lp[BB * 4];           // partial sum per (b,quarter)
__device__ float g_wa[BB * TT];          // fallback w buffer if out_a == null

// ---------------- cp.async helpers ----------------
__device__ __forceinline__ void cp_async16(void* smem_dst, const void* gmem_src) {
    unsigned s = (unsigned)__cvta_generic_to_shared(smem_dst);
    asm volatile("cp.async.cg.shared.global [%0], [%1], 16;\n" :: "r"(s), "l"(gmem_src));
}
__device__ __forceinline__ void cp_commit() {
    asm volatile("cp.async.commit_group;\n");
}
template <int N>
__device__ __forceinline__ void cp_wait() {
    asm volatile("cp.async.wait_group %0;\n" :: "n"(N));
}

// ================== K0: per-batch prologue (grid BB x 256) ==================
__device__ __forceinline__ int blockReduceSumInt256(int v, int* sred) {
    #pragma unroll
    for (int o = 16; o; o >>= 1) v += __shfl_xor_sync(0xffffffffu, v, o);
    int warp = threadIdx.x >> 5, lane = threadIdx.x & 31;
    if (lane == 0) sred[warp] = v;
    __syncthreads();
    if (warp == 0) {
        int x = (lane < 8) ? sred[lane] : 0;
        #pragma unroll
        for (int o = 4; o; o >>= 1) x += __shfl_xor_sync(0xffffffffu, x, o);
        if (lane == 0) sred[0] = x;
    }
    __syncthreads();
    int r = sred[0];
    __syncthreads();
    return r;
}

__global__ __launch_bounds__(256)
void k0_prologue(const float* __restrict__ input,   // [B,T,D]
                 const int*   __restrict__ mask,    // [B,T]
                 const float* __restrict__ Wt,      // [D,H]
                 const float* __restrict__ Wx)      // [D,H]
{
    __shared__ float s_q[HH], s_lv[DD];
    __shared__ float s_qp[2][HH];
    __shared__ float s_rp[2][DD];
    __shared__ int   s_redi[8];

    const int b   = blockIdx.x;
    const int tid = threadIdx.x;

    const float* __restrict__ gx = input + (size_t)b * TT * DD;
    const int*   __restrict__ mb = mask  + (size_t)b * TT;

    int msum = blockReduceSumInt256(mb[tid] + mb[tid + 256], s_redi);
    int last = msum - 1; if (last < 0) last = 0;

    if (tid < DD) s_lv[tid] = gx[(size_t)last * DD + tid];
    __syncthreads();

    // q[h] = sum_d lv[d] * Wt[d,h]  (2-way d-chunk)
    {
        int c = tid >> 7, h = tid & 127;
        float acc = 0.0f;
        #pragma unroll 8
        for (int d = c * 64; d < c * 64 + 64; d++)
            acc += s_lv[d] * Wt[d * HH + h];
        s_qp[c][h] = acc;
    }
    __syncthreads();
    if (tid < HH) s_q[tid] = s_qp[0][tid] + s_qp[1][tid];
    __syncthreads();

    // r[d] = sum_h Wx[d,h] * q[h]  (2-way h-chunk, float4)
    {
        int c = tid >> 7, d = tid & 127;
        const float4* wrow = (const float4*)(Wx + (size_t)d * HH) + c * 16;
        const float4* qv   = (const float4*)s_q + c * 16;
        float acc = 0.0f;
        #pragma unroll
        for (int j = 0; j < 16; j++) {
            float4 w = wrow[j], qq = qv[j];
            acc += w.x * qq.x + w.y * qq.y + w.z * qq.z + w.w * qq.w;
        }
        s_rp[c][d] = acc;
    }
    __syncthreads();
    if (tid < DD) g_r[b * DD + tid] = s_rp[0][tid] + s_rp[1][tid];
}

// ================== KA: streaming pass (grid BB*4 x 128) ==================
// CTA = (b, quarter). 4 warps x 32 rows. Per-warp cp.async ring,
// 3 stages x 2 rows (1KB), lead-2. No block barriers in the main loop.
#define KA_STAGES 3
#define KA_STAGE_F4 64                  // 2 rows * 32 float4

__global__ __launch_bounds__(128, 12)
void ka_stream(const float* __restrict__ input,
               const int*   __restrict__ mask,
               const float* __restrict__ rate,
               float* __restrict__ wa)              // unnormalized weights [B,T]
{
    __shared__ float4 s_ring[4][KA_STAGES * KA_STAGE_F4];   // 12 KB
    __shared__ float  s_r[DD];
    __shared__ int    s_m[128];
    __shared__ float  s_v[4][DD];
    __shared__ float  s_l[4];

    const int x    = blockIdx.x;
    const int b    = x >> 2;
    const int qt   = x & 3;
    const int tid  = threadIdx.x;
    const int w    = tid >> 5, lane = tid & 31;
    const int t0   = qt * 128;
    const int half = lane >> 4;

    // warp's 32 rows start at t0 + w*32
    const float4* __restrict__ grow =
        (const float4*)(input + ((size_t)b * TT + t0 + w * 32) * DD);
    float4* __restrict__ myring = &s_ring[w][0];

    // prefetch batches 0,1 (2 rows each)
    #pragma unroll
    for (int j = 0; j < 2; j++) {
        float4* slot = myring + j * KA_STAGE_F4;
        cp_async16(slot + lane,      grow + j * 64 + lane);
        cp_async16(slot + 32 + lane, grow + j * 64 + 32 + lane);
        cp_commit();
    }

    // prologue loads (overlap with prefetch)
    s_r[tid] = g_r[b * DD + tid];
    s_m[tid] = mask[(size_t)b * TT + t0 + tid];
    __syncthreads();

    const float srate = __fdividef(1.0f, 1.0f + __expf(-rate[0]));
    const float4 rr = ((const float4*)s_r)[lane];

    float4 acc = make_float4(0.f, 0.f, 0.f, 0.f);
    float  lacc = 0.0f;

    #pragma unroll 4
    for (int i = 0; i < 16; i++) {
        const int nb = i + 2;
        if (nb < 16) {
            float4* slot = myring + (nb % KA_STAGES) * KA_STAGE_F4;
            cp_async16(slot + lane,      grow + nb * 64 + lane);
            cp_async16(slot + 32 + lane, grow + nb * 64 + 32 + lane);
        }
        cp_commit();                      // commit every iter -> wait<2> = batch i done
        cp_wait<2>();

        const float4* slot = myring + (i % KA_STAGES) * KA_STAGE_F4;
        const float4 c0 = slot[lane];
        const float4 c1 = slot[32 + lane];

        float p0 = c0.x * rr.x + c0.y * rr.y + c0.z * rr.z + c0.w * rr.w;
        float p1 = c1.x * rr.x + c1.y * rr.y + c1.z * rr.z + c1.w * rr.w;
        p0 += __shfl_xor_sync(0xffffffffu, p0, 16);
        p1 += __shfl_xor_sync(0xffffffffu, p1, 16);
        float p = half ? p1 : p0;
        p += __shfl_xor_sync(0xffffffffu, p, 8);
        p += __shfl_xor_sync(0xffffffffu, p, 4);
        p += __shfl_xor_sync(0xffffffffu, p, 2);
        p += __shfl_xor_sync(0xffffffffu, p, 1);
        // lanes 0-15: dot(row 2i), lanes 16-31: dot(row 2i+1)

        const int tl = w * 32 + 2 * i + half;     // local t in [0,128)
        const int tg = t0 + tl;                   // global t for decay
        float sig   = __fdividef(1.0f, 1.0f + __expf(-p));
        float denom = srate * (__logf(2.72f + (1.0f - sig)) * (float)(TT - tg));
        float e     = fmaxf(__fdividef(sig, denom), 0.0f);
        float wgt   = (s_m[tl] != 0) ? __expf(e) : 0.0f;

        if ((lane & 15) == 0) {
            wa[(size_t)b * TT + tg] = wgt;        // unnormalized
            lacc += wgt;
        }
        float w0 = __shfl_sync(0xffffffffu, wgt, 0);
        float w1 = __shfl_sync(0xffffffffu, wgt, 16);

        acc.x += w0 * c0.x + w1 * c1.x;
        acc.y += w0 * c0.y + w1 * c1.y;
        acc.z += w0 * c0.z + w1 * c1.z;
        acc.w += w0 * c0.w + w1 * c1.w;
    }

    // epilogue: combine 4 warps' partials
    ((float4*)&s_v[w][0])[lane] = acc;
    float lw = __shfl_sync(0xffffffffu, lacc, 0) + __shfl_sync(0xffffffffu, lacc, 16);
    if (lane == 0) s_l[w] = lw;
    __syncthreads();

    if (tid == 0) g_lp[x] = s_l[0] + s_l[1] + s_l[2] + s_l[3];
    g_vp[(size_t)x * DD + tid] = s_v[0][tid] + s_v[1][tid] + s_v[2][tid] + s_v[3][tid];
}

// ================== KB: finalize (grid BB x 128) ==================
__global__ __launch_bounds__(128)
void kb_finalize(float* __restrict__ out_v,   // [B,D] or null
                 float* __restrict__ out_a,   // [B,T] or null (holds unnormalized w)
                 const float* __restrict__ wa)
{
    const int b   = blockIdx.x;
    const int tid = threadIdx.x;

    float l = g_lp[4 * b] + g_lp[4 * b + 1] + g_lp[4 * b + 2] + g_lp[4 * b + 3];
    float inv = __fdividef(1.0f, l);

    if (out_v) {
        float v = g_vp[(size_t)(4 * b    ) * DD + tid]
                + g_vp[(size_t)(4 * b + 1) * DD + tid]
                + g_vp[(size_t)(4 * b + 2) * DD + tid]
                + g_vp[(size_t)(4 * b + 3) * DD + tid];
        out_v[(size_t)b * DD + tid] = v * inv;
    }
    if (out_a) {
        #pragma unroll
        for (int j = 0; j < 4; j++) {
            size_t idx = (size_t)b * TT + j * 128 + tid;
            out_a[idx] = wa[idx] * inv;
        }
    }
}

// ================== launch ==================
extern "C" void kernel_launch(void* const* d_in, const int* in_sizes, int n_in,
                              void* d_out, int out_size) {
    const float* input = (const float*)d_in[0];
    const int*   mask  = (const int*)  d_in[1];
    const float* Wt    = (const float*)d_in[2];
    const float* Wx    = (const float*)d_in[3];
    const float* rate  = (const float*)d_in[4];

    float* out = (float*)d_out;
    float* out_v = nullptr;
    float* out_a = nullptr;

    if (out_size == BB * DD + BB * TT) {        // (v, a) concatenated
        out_v = out;
        out_a = out + BB * DD;
    } else if (out_size == BB * DD) {           // v only
        out_v = out;
    } else {                                    // a only
        out_a = out;
    }

    // weight buffer: use out_a directly when present, else device scratch
    float* wa;
    if (out_a) {
        wa = out_a;
    } else {
        cudaGetSymbolAddress((void**)&wa, g_wa);   // address query only, no alloc
    }

    k0_prologue<<<BB, 256>>>(input, mask, Wt, Wx);
    ka_stream  <<<BB * 4, 128>>>(input, mask, rate, wa);
    kb_finalize<<<BB, 128>>>(out_v, out_a, wa);
}

// round 8
// speedup vs baseline: 1.0145x; 1.0145x over previous
#include <cuda_runtime.h>
#include <math_constants.h>

// Problem constants: B=512, T=512, D=128, H=128
#define BB 512
#define TT 512
#define DD 128
#define HH 128

// ---------------- scratch (static __device__ allowed) ----------------
__device__ float g_r [BB * DD];          // r vector per batch      (256 KB)
__device__ float g_vp[BB * 4 * DD];      // partial v per (b,quarter) (1 MB)
__device__ float g_lp[BB * 4];           // partial sum per (b,quarter)
__device__ float g_wa[BB * TT];          // fallback w buffer if out_a == null

// ---------------- cp.async helpers ----------------
__device__ __forceinline__ void cp_async16(void* smem_dst, const void* gmem_src) {
    unsigned s = (unsigned)__cvta_generic_to_shared(smem_dst);
    asm volatile("cp.async.cg.shared.global [%0], [%1], 16;\n" :: "r"(s), "l"(gmem_src));
}
__device__ __forceinline__ void cp_commit() {
    asm volatile("cp.async.commit_group;\n");
}
template <int N>
__device__ __forceinline__ void cp_wait() {
    asm volatile("cp.async.wait_group %0;\n" :: "n"(N));
}

// ================== K0: per-batch prologue (grid BB x 512) ==================
// Redesigned for load parallelism: q-phase uses row-major float4 reads of Wt
// (8 per thread, fully unrolled) with a 16-way SMEM partial reduction.
__global__ __launch_bounds__(512)
void k0_prologue(const float* __restrict__ input,   // [B,T,D]
                 const int*   __restrict__ mask,    // [B,T]
                 const float* __restrict__ Wt,      // [D,H]
                 const float* __restrict__ Wx)      // [D,H]
{
    __shared__ float  s_lv[DD];
    __shared__ float4 s_q4[HH / 4];          // q as 32 float4
    __shared__ float4 s_qp4[16][HH / 4];     // 16 d-group partials (8 KB)
    __shared__ float  s_rp[4][DD];           // 4 h-chunk partials  (2 KB)
    __shared__ int    s_redi[16];

    const int b   = blockIdx.x;
    const int tid = threadIdx.x;
    const int warp = tid >> 5, lane = tid & 31;

    const float* __restrict__ gx = input + (size_t)b * TT * DD;

    // ---- mask sum: one element per thread (512 == TT) ----
    int mv = mask[(size_t)b * TT + tid];
    #pragma unroll
    for (int o = 16; o; o >>= 1) mv += __shfl_xor_sync(0xffffffffu, mv, o);
    if (lane == 0) s_redi[warp] = mv;
    __syncthreads();
    if (warp == 0) {
        int x = (lane < 16) ? s_redi[lane] : 0;
        #pragma unroll
        for (int o = 8; o; o >>= 1) x += __shfl_xor_sync(0xffffffffu, x, o);
        if (lane == 0) s_redi[0] = x;
    }
    __syncthreads();
    int last = s_redi[0] - 1; if (last < 0) last = 0;

    // ---- last_visit (float4 by 32 threads) ----
    if (tid < 32)
        ((float4*)s_lv)[tid] = ((const float4*)(gx + (size_t)last * DD))[tid];
    __syncthreads();

    // ---- q[h] = sum_d lv[d] * Wt[d,h] ----
    // thread = (g = d-group of 8, hq = h-quad). Row-major float4 reads, MLP=8.
    {
        const int hq = tid & 31;          // 0..31 float4 column
        const int g  = tid >> 5;          // 0..15 -> d in [8g, 8g+8)
        const float4* wt4 = (const float4*)Wt;
        float4 a = make_float4(0.f, 0.f, 0.f, 0.f);
        #pragma unroll
        for (int j = 0; j < 8; j++) {
            const int d = g * 8 + j;
            const float lv = s_lv[d];
            const float4 w = wt4[d * 32 + hq];
            a.x += lv * w.x; a.y += lv * w.y; a.z += lv * w.z; a.w += lv * w.w;
        }
        s_qp4[g][hq] = a;
    }
    __syncthreads();
    if (tid < 32) {
        float4 a = s_qp4[0][tid];
        #pragma unroll
        for (int g = 1; g < 16; g++) {
            float4 c = s_qp4[g][tid];
            a.x += c.x; a.y += c.y; a.z += c.z; a.w += c.w;
        }
        s_q4[tid] = a;
    }
    __syncthreads();

    // ---- r[d] = sum_h Wx[d,h] * q[h]  (4-way h-chunk, float4 rows, MLP=8) ----
    {
        const int c = tid >> 7;           // 0..3
        const int d = tid & 127;
        const float4* wrow = (const float4*)(Wx + (size_t)d * HH) + c * 8;
        const float4* qv   = s_q4 + c * 8;
        float acc = 0.0f;
        #pragma unroll
        for (int j = 0; j < 8; j++) {
            float4 w = wrow[j], qq = qv[j];
            acc += w.x * qq.x + w.y * qq.y + w.z * qq.z + w.w * qq.w;
        }
        s_rp[c][d] = acc;
    }
    __syncthreads();
    if (tid < DD)
        g_r[b * DD + tid] = s_rp[0][tid] + s_rp[1][tid] + s_rp[2][tid] + s_rp[3][tid];
}

// ================== KA: streaming pass (grid BB*4 x 128) ==================
// CTA = (b, quarter). 4 warps x 32 rows. Per-warp cp.async ring,
// 3 stages x 2 rows (1KB), lead-2. No block barriers in the main loop.
#define KA_STAGES 3
#define KA_STAGE_F4 64                  // 2 rows * 32 float4

__global__ __launch_bounds__(128, 12)
void ka_stream(const float* __restrict__ input,
               const int*   __restrict__ mask,
               const float* __restrict__ rate,
               float* __restrict__ wa)              // unnormalized weights [B,T]
{
    __shared__ float4 s_ring[4][KA_STAGES * KA_STAGE_F4];   // 12 KB
    __shared__ float  s_r[DD];
    __shared__ int    s_m[128];
    __shared__ float  s_v[4][DD];
    __shared__ float  s_l[4];

    const int x    = blockIdx.x;
    const int b    = x >> 2;
    const int qt   = x & 3;
    const int tid  = threadIdx.x;
    const int w    = tid >> 5, lane = tid & 31;
    const int t0   = qt * 128;
    const int half = lane >> 4;

    // warp's 32 rows start at t0 + w*32
    const float4* __restrict__ grow =
        (const float4*)(input + ((size_t)b * TT + t0 + w * 32) * DD);
    float4* __restrict__ myring = &s_ring[w][0];

    // prefetch batches 0,1 (2 rows each)
    #pragma unroll
    for (int j = 0; j < 2; j++) {
        float4* slot = myring + j * KA_STAGE_F4;
        cp_async16(slot + lane,      grow + j * 64 + lane);
        cp_async16(slot + 32 + lane, grow + j * 64 + 32 + lane);
        cp_commit();
    }

    // prologue loads (overlap with prefetch)
    s_r[tid] = g_r[b * DD + tid];
    s_m[tid] = mask[(size_t)b * TT + t0 + tid];
    __syncthreads();

    const float srate = __fdividef(1.0f, 1.0f + __expf(-rate[0]));
    const float4 rr = ((const float4*)s_r)[lane];

    float4 acc = make_float4(0.f, 0.f, 0.f, 0.f);
    float  lacc = 0.0f;

    #pragma unroll 4
    for (int i = 0; i < 16; i++) {
        const int nb = i + 2;
        if (nb < 16) {
            float4* slot = myring + (nb % KA_STAGES) * KA_STAGE_F4;
            cp_async16(slot + lane,      grow + nb * 64 + lane);
            cp_async16(slot + 32 + lane, grow + nb * 64 + 32 + lane);
        }
        cp_commit();                      // commit every iter -> wait<2> = batch i done
        cp_wait<2>();

        const float4* slot = myring + (i % KA_STAGES) * KA_STAGE_F4;
        const float4 c0 = slot[lane];
        const float4 c1 = slot[32 + lane];

        float p0 = c0.x * rr.x + c0.y * rr.y + c0.z * rr.z + c0.w * rr.w;
        float p1 = c1.x * rr.x + c1.y * rr.y + c1.z * rr.z + c1.w * rr.w;
        p0 += __shfl_xor_sync(0xffffffffu, p0, 16);
        p1 += __shfl_xor_sync(0xffffffffu, p1, 16);
        float p = half ? p1 : p0;
        p += __shfl_xor_sync(0xffffffffu, p, 8);
        p += __shfl_xor_sync(0xffffffffu, p, 4);
        p += __shfl_xor_sync(0xffffffffu, p, 2);
        p += __shfl_xor_sync(0xffffffffu, p, 1);
        // lanes 0-15: dot(row 2i), lanes 16-31: dot(row 2i+1)

        const int tl = w * 32 + 2 * i + half;     // local t in [0,128)
        const int tg = t0 + tl;                   // global t for decay
        float sig   = __fdividef(1.0f, 1.0f + __expf(-p));
        float denom = srate * (__logf(2.72f + (1.0f - sig)) * (float)(TT - tg));
        float e     = fmaxf(__fdividef(sig, denom), 0.0f);
        float wgt   = (s_m[tl] != 0) ? __expf(e) : 0.0f;

        if ((lane & 15) == 0) {
            wa[(size_t)b * TT + tg] = wgt;        // unnormalized
            lacc += wgt;
        }
        float w0 = __shfl_sync(0xffffffffu, wgt, 0);
        float w1 = __shfl_sync(0xffffffffu, wgt, 16);

        acc.x += w0 * c0.x + w1 * c1.x;
        acc.y += w0 * c0.y + w1 * c1.y;
        acc.z += w0 * c0.z + w1 * c1.z;
        acc.w += w0 * c0.w + w1 * c1.w;
    }

    // epilogue: combine 4 warps' partials
    ((float4*)&s_v[w][0])[lane] = acc;
    float lw = __shfl_sync(0xffffffffu, lacc, 0) + __shfl_sync(0xffffffffu, lacc, 16);
    if (lane == 0) s_l[w] = lw;
    __syncthreads();

    if (tid == 0) g_lp[x] = s_l[0] + s_l[1] + s_l[2] + s_l[3];
    g_vp[(size_t)x * DD + tid] = s_v[0][tid] + s_v[1][tid] + s_v[2][tid] + s_v[3][tid];
}

// ================== KB: finalize (grid BB x 128) ==================
__global__ __launch_bounds__(128)
void kb_finalize(float* __restrict__ out_v,   // [B,D] or null
                 float* __restrict__ out_a,   // [B,T] or null (holds unnormalized w)
                 const float* __restrict__ wa)
{
    const int b   = blockIdx.x;
    const int tid = threadIdx.x;

    float l = g_lp[4 * b] + g_lp[4 * b + 1] + g_lp[4 * b + 2] + g_lp[4 * b + 3];
    float inv = __fdividef(1.0f, l);

    if (out_v) {
        float v = g_vp[(size_t)(4 * b    ) * DD + tid]
                + g_vp[(size_t)(4 * b + 1) * DD + tid]
                + g_vp[(size_t)(4 * b + 2) * DD + tid]
                + g_vp[(size_t)(4 * b + 3) * DD + tid];
        out_v[(size_t)b * DD + tid] = v * inv;
    }
    if (out_a) {
        #pragma unroll
        for (int j = 0; j < 4; j++) {
            size_t idx = (size_t)b * TT + j * 128 + tid;
            out_a[idx] = wa[idx] * inv;
        }
    }
}

// ================== launch ==================
extern "C" void kernel_launch(void* const* d_in, const int* in_sizes, int n_in,
                              void* d_out, int out_size) {
    const float* input = (const float*)d_in[0];
    const int*   mask  = (const int*)  d_in[1];
    const float* Wt    = (const float*)d_in[2];
    const float* Wx    = (const float*)d_in[3];
    const float* rate  = (const float*)d_in[4];

    float* out = (float*)d_out;
    float* out_v = nullptr;
    float* out_a = nullptr;

    if (out_size == BB * DD + BB * TT) {        // (v, a) concatenated
        out_v = out;
        out_a = out + BB * DD;
    } else if (out_size == BB * DD) {           // v only
        out_v = out;
    } else {                                    // a only
        out_a = out;
    }

    // weight buffer: use out_a directly when present, else device scratch
    float* wa;
    if (out_a) {
        wa = out_a;
    } else {
        cudaGetSymbolAddress((void**)&wa, g_wa);   // address query only, no alloc
    }

    k0_prologue<<<BB, 512>>>(input, mask, Wt, Wx);
    ka_stream  <<<BB * 4, 128>>>(input, mask, rate, wa);
    kb_finalize<<<BB, 128>>>(out_v, out_a, wa);
}

// round 9
// speedup vs baseline: 1.2066x; 1.1893x over previous
#include <cuda_runtime.h>
#include <math_constants.h>

// Problem constants: B=512, T=512, D=128, H=128
#define BB 512
#define TT 512
#define DD 128
#define HH 128

// ---------------- scratch (static __device__ allowed) ----------------
__device__ float g_r [BB * DD];          // r vector per batch      (256 KB)
__device__ float g_vp[BB * 4 * DD];      // partial v per (b,quarter) (1 MB)
__device__ float g_lp[BB * 4];           // partial sum per (b,quarter)
__device__ float g_wa[BB * TT];          // fallback w buffer if out_a == null

// ---------------- cp.async helpers ----------------
__device__ __forceinline__ void cp_async16(void* smem_dst, const void* gmem_src) {
    unsigned s = (unsigned)__cvta_generic_to_shared(smem_dst);
    asm volatile("cp.async.cg.shared.global [%0], [%1], 16;\n" :: "r"(s), "l"(gmem_src));
}
__device__ __forceinline__ void cp_commit() {
    asm volatile("cp.async.commit_group;\n");
}
template <int N>
__device__ __forceinline__ void cp_wait() {
    asm volatile("cp.async.wait_group %0;\n" :: "n"(N));
}

// ================== K0: prologue, 4 batches/CTA (grid BB/4 x 256) ==================
// One wave (128 CTAs). Weights staged once per CTA: Wt via cp.async (overlapped
// with per-warp mask chains), Wx transposed into padded SMEM for conflict-free
// R-stage reads. Q/R stages amortize every weight element over 4 batches.
#define WXT_PAD 129

__global__ __launch_bounds__(256)
void k0_prologue(const float* __restrict__ input,   // [B,T,D]
                 const int*   __restrict__ mask,    // [B,T]
                 const float* __restrict__ Wt,      // [D,H]
                 const float* __restrict__ Wx)      // [D,H]
{
    extern __shared__ float dyn[];
    float* sWt  = dyn;                   // [DD*HH]        64 KB, layout [d][h]
    float* sWxT = dyn + DD * HH;         // [HH][WXT_PAD]  ~64.5 KB, sWxT[h][d]=Wx[d][h]

    __shared__ float4 s_lvT4[DD];        // lv packed per d: (.x=b0 .. .w=b3)
    __shared__ float4 s_qp4[2][HH];      // Q partials (2 d-chunks)
    __shared__ float4 s_q4[HH];          // q packed per h
    __shared__ float4 s_rp4[2][DD];      // R partials (2 h-chunks)

    const int tid  = threadIdx.x;
    const int warp = tid >> 5, lane = tid & 31;
    const int b0   = blockIdx.x * 4;

    // ---- 1. stage Wt -> sWt via cp.async (64 KB, 16 x 16B per thread) ----
    {
        const float4* src = (const float4*)Wt;
        float4* dst = (float4*)sWt;
        #pragma unroll
        for (int j = 0; j < 16; j++)
            cp_async16(dst + tid + j * 256, src + tid + j * 256);
        cp_commit();
    }

    // ---- 2. warps 0-3: mask sum + last_visit gather for batch b0+warp ----
    if (warp < 4) {
        const int bb = b0 + warp;
        const int4* m4 = (const int4*)(mask + (size_t)bb * TT);
        int s = 0;
        #pragma unroll
        for (int j = 0; j < 4; j++) {
            int4 m = m4[lane + 32 * j];
            s += m.x + m.y + m.z + m.w;
        }
        #pragma unroll
        for (int o = 16; o; o >>= 1) s += __shfl_xor_sync(0xffffffffu, s, o);
        int last = s - 1; if (last < 0) last = 0;

        const float4* lvsrc = (const float4*)(input + ((size_t)bb * TT + last) * DD);
        float4 lv = lvsrc[lane];                       // d = 4*lane .. 4*lane+3
        float* s_lvT = (float*)s_lvT4;
        s_lvT[(4 * lane + 0) * 4 + warp] = lv.x;
        s_lvT[(4 * lane + 1) * 4 + warp] = lv.y;
        s_lvT[(4 * lane + 2) * 4 + warp] = lv.z;
        s_lvT[(4 * lane + 3) * 4 + warp] = lv.w;
    }

    // ---- 3. all threads: transpose Wx into sWxT (overlaps mask latency) ----
    {
        const float4* wx4 = (const float4*)Wx;
        #pragma unroll
        for (int j = 0; j < 16; j++) {
            int idx = tid + j * 256;                   // float4 index
            int d = idx >> 5, h4 = idx & 31;           // row d, h quad
            float4 w = wx4[idx];
            sWxT[(4 * h4 + 0) * WXT_PAD + d] = w.x;
            sWxT[(4 * h4 + 1) * WXT_PAD + d] = w.y;
            sWxT[(4 * h4 + 2) * WXT_PAD + d] = w.z;
            sWxT[(4 * h4 + 3) * WXT_PAD + d] = w.w;
        }
    }

    cp_wait<0>();
    __syncthreads();            // sWt, sWxT, s_lvT4 all visible

    // ---- 4. Q stage: q[b][h] = sum_d lv[b][d] * Wt[d][h] ----
    {
        const int c = tid >> 7, h = tid & 127;
        float4 acc = make_float4(0.f, 0.f, 0.f, 0.f);
        #pragma unroll 8
        for (int d = c * 64; d < c * 64 + 64; d++) {
            float  w  = sWt[d * HH + h];               // lanes->h consecutive
            float4 lv = s_lvT4[d];                     // broadcast
            acc.x += w * lv.x; acc.y += w * lv.y;
            acc.z += w * lv.z; acc.w += w * lv.w;
        }
        s_qp4[c][h] = acc;
    }
    __syncthreads();
    if (tid < HH) {
        float4 a = s_qp4[0][tid], b = s_qp4[1][tid];
        s_q4[tid] = make_float4(a.x + b.x, a.y + b.y, a.z + b.z, a.w + b.w);
    }
    __syncthreads();

    // ---- 5. R stage: r[b][d] = sum_h Wx[d][h] * q[b][h] ----
    {
        const int c = tid >> 7, d = tid & 127;
        float4 acc = make_float4(0.f, 0.f, 0.f, 0.f);
        #pragma unroll 8
        for (int h = c * 64; h < c * 64 + 64; h++) {
            float  w = sWxT[h * WXT_PAD + d];          // lanes->d consecutive
            float4 q = s_q4[h];                        // broadcast
            acc.x += w * q.x; acc.y += w * q.y;
            acc.z += w * q.z; acc.w += w * q.w;
        }
        s_rp4[c][d] = acc;
    }
    __syncthreads();
    if (tid < DD) {
        float4 a = s_rp4[0][tid], b = s_rp4[1][tid];
        g_r[(size_t)(b0 + 0) * DD + tid] = a.x + b.x;
        g_r[(size_t)(b0 + 1) * DD + tid] = a.y + b.y;
        g_r[(size_t)(b0 + 2) * DD + tid] = a.z + b.z;
        g_r[(size_t)(b0 + 3) * DD + tid] = a.w + b.w;
    }
}

// ================== KA: streaming pass (grid BB*4 x 128) ==================
// CTA = (b, quarter). 4 warps x 32 rows. Per-warp cp.async ring,
// 3 stages x 2 rows (1KB), lead-2. No block barriers in the main loop.
#define KA_STAGES 3
#define KA_STAGE_F4 64                  // 2 rows * 32 float4

__global__ __launch_bounds__(128, 12)
void ka_stream(const float* __restrict__ input,
               const int*   __restrict__ mask,
               const float* __restrict__ rate,
               float* __restrict__ wa)              // unnormalized weights [B,T]
{
    __shared__ float4 s_ring[4][KA_STAGES * KA_STAGE_F4];   // 12 KB
    __shared__ float  s_r[DD];
    __shared__ int    s_m[128];
    __shared__ float  s_v[4][DD];
    __shared__ float  s_l[4];

    const int x    = blockIdx.x;
    const int b    = x >> 2;
    const int qt   = x & 3;
    const int tid  = threadIdx.x;
    const int w    = tid >> 5, lane = tid & 31;
    const int t0   = qt * 128;
    const int half = lane >> 4;

    // warp's 32 rows start at t0 + w*32
    const float4* __restrict__ grow =
        (const float4*)(input + ((size_t)b * TT + t0 + w * 32) * DD);
    float4* __restrict__ myring = &s_ring[w][0];

    // prefetch batches 0,1 (2 rows each)
    #pragma unroll
    for (int j = 0; j < 2; j++) {
        float4* slot = myring + j * KA_STAGE_F4;
        cp_async16(slot + lane,      grow + j * 64 + lane);
        cp_async16(slot + 32 + lane, grow + j * 64 + 32 + lane);
        cp_commit();
    }

    // prologue loads (overlap with prefetch)
    s_r[tid] = g_r[b * DD + tid];
    s_m[tid] = mask[(size_t)b * TT + t0 + tid];
    __syncthreads();

    const float srate = __fdividef(1.0f, 1.0f + __expf(-rate[0]));
    const float4 rr = ((const float4*)s_r)[lane];

    float4 acc = make_float4(0.f, 0.f, 0.f, 0.f);
    float  lacc = 0.0f;

    #pragma unroll 4
    for (int i = 0; i < 16; i++) {
        const int nb = i + 2;
        if (nb < 16) {
            float4* slot = myring + (nb % KA_STAGES) * KA_STAGE_F4;
            cp_async16(slot + lane,      grow + nb * 64 + lane);
            cp_async16(slot + 32 + lane, grow + nb * 64 + 32 + lane);
        }
        cp_commit();                      // commit every iter -> wait<2> = batch i done
        cp_wait<2>();

        const float4* slot = myring + (i % KA_STAGES) * KA_STAGE_F4;
        const float4 c0 = slot[lane];
        const float4 c1 = slot[32 + lane];

        float p0 = c0.x * rr.x + c0.y * rr.y + c0.z * rr.z + c0.w * rr.w;
        float p1 = c1.x * rr.x + c1.y * rr.y + c1.z * rr.z + c1.w * rr.w;
        p0 += __shfl_xor_sync(0xffffffffu, p0, 16);
        p1 += __shfl_xor_sync(0xffffffffu, p1, 16);
        float p = half ? p1 : p0;
        p += __shfl_xor_sync(0xffffffffu, p, 8);
        p += __shfl_xor_sync(0xffffffffu, p, 4);
        p += __shfl_xor_sync(0xffffffffu, p, 2);
        p += __shfl_xor_sync(0xffffffffu, p, 1);
        // lanes 0-15: dot(row 2i), lanes 16-31: dot(row 2i+1)

        const int tl = w * 32 + 2 * i + half;     // local t in [0,128)
        const int tg = t0 + tl;                   // global t for decay
        float sig   = __fdividef(1.0f, 1.0f + __expf(-p));
        float denom = srate * (__logf(2.72f + (1.0f - sig)) * (float)(TT - tg));
        float e     = fmaxf(__fdividef(sig, denom), 0.0f);
        float wgt   = (s_m[tl] != 0) ? __expf(e) : 0.0f;

        if ((lane & 15) == 0) {
            wa[(size_t)b * TT + tg] = wgt;        // unnormalized
            lacc += wgt;
        }
        float w0 = __shfl_sync(0xffffffffu, wgt, 0);
        float w1 = __shfl_sync(0xffffffffu, wgt, 16);

        acc.x += w0 * c0.x + w1 * c1.x;
        acc.y += w0 * c0.y + w1 * c1.y;
        acc.z += w0 * c0.z + w1 * c1.z;
        acc.w += w0 * c0.w + w1 * c1.w;
    }

    // epilogue: combine 4 warps' partials
    ((float4*)&s_v[w][0])[lane] = acc;
    float lw = __shfl_sync(0xffffffffu, lacc, 0) + __shfl_sync(0xffffffffu, lacc, 16);
    if (lane == 0) s_l[w] = lw;
    __syncthreads();

    if (tid == 0) g_lp[x] = s_l[0] + s_l[1] + s_l[2] + s_l[3];
    g_vp[(size_t)x * DD + tid] = s_v[0][tid] + s_v[1][tid] + s_v[2][tid] + s_v[3][tid];
}

// ================== KB: finalize (grid BB x 128) ==================
__global__ __launch_bounds__(128)
void kb_finalize(float* __restrict__ out_v,   // [B,D] or null
                 float* __restrict__ out_a,   // [B,T] or null (holds unnormalized w)
                 const float* __restrict__ wa)
{
    const int b   = blockIdx.x;
    const int tid = threadIdx.x;

    float l = g_lp[4 * b] + g_lp[4 * b + 1] + g_lp[4 * b + 2] + g_lp[4 * b + 3];
    float inv = __fdividef(1.0f, l);

    if (out_v) {
        float v = g_vp[(size_t)(4 * b    ) * DD + tid]
                + g_vp[(size_t)(4 * b + 1) * DD + tid]
                + g_vp[(size_t)(4 * b + 2) * DD + tid]
                + g_vp[(size_t)(4 * b + 3) * DD + tid];
        out_v[(size_t)b * DD + tid] = v * inv;
    }
    if (out_a) {
        #pragma unroll
        for (int j = 0; j < 4; j++) {
            size_t idx = (size_t)b * TT + j * 128 + tid;
            out_a[idx] = wa[idx] * inv;
        }
    }
}

// ================== launch ==================
extern "C" void kernel_launch(void* const* d_in, const int* in_sizes, int n_in,
                              void* d_out, int out_size) {
    const float* input = (const float*)d_in[0];
    const int*   mask  = (const int*)  d_in[1];
    const float* Wt    = (const float*)d_in[2];
    const float* Wx    = (const float*)d_in[3];
    const float* rate  = (const float*)d_in[4];

    float* out = (float*)d_out;
    float* out_v = nullptr;
    float* out_a = nullptr;

    if (out_size == BB * DD + BB * TT) {        // (v, a) concatenated
        out_v = out;
        out_a = out + BB * DD;
    } else if (out_size == BB * DD) {           // v only
        out_v = out;
    } else {                                    // a only
        out_a = out;
    }

    // weight buffer: use out_a directly when present, else device scratch
    float* wa;
    if (out_a) {
        wa = out_a;
    } else {
        cudaGetSymbolAddress((void**)&wa, g_wa);   // address query only, no alloc
    }

    const int k0_smem = (DD * HH + HH * WXT_PAD) * (int)sizeof(float);   // ~128.5 KB
    static int smem_set = 0;
    if (!smem_set) {
        cudaFuncSetAttribute(k0_prologue,
                             cudaFuncAttributeMaxDynamicSharedMemorySize, k0_smem);
        smem_set = 1;
    }

    k0_prologue<<<BB / 4, 256, k0_smem>>>(input, mask, Wt, Wx);
    ka_stream  <<<BB * 4, 128>>>(input, mask, rate, wa);
    kb_finalize<<<BB, 128>>>(out_v, out_a, wa);
}